// round 7
// baseline (speedup 1.0000x reference)
#include <cuda_runtime.h>
#include <math.h>

#define NB 262144
#define NP 8
#define NT 128
#define NBLOCKS (NB / NT)
#define MAXC 24

__device__ double g_part[NBLOCKS];
__device__ unsigned int g_ticket;

__global__ void __launch_bounds__(NT, 6)
ciou_kernel(const float* __restrict__ A, const float* __restrict__ Bm,
            float* __restrict__ out) {
    // [slot][tid] layout: bank index = tid%32, conflict-free even when
    // lanes use different slot indices.
    __shared__ float s_cx[MAXC][NT];
    __shared__ float s_cy[MAXC][NT];
    __shared__ float s_an[MAXC][NT];

    const int tid = threadIdx.x;
    const int b   = blockIdx.x * NT + tid;

    double val;
    {
        // ---- load both octagons (registers; all later indexing is const) ----
        float axv[NP], ayv[NP], bxv[NP], byv[NP];
        const float4* pa4 = (const float4*)(A  + (size_t)b * 16);
        const float4* pb4 = (const float4*)(Bm + (size_t)b * 16);
        #pragma unroll
        for (int i = 0; i < 4; i++) {
            float4 fa = pa4[i], fb = pb4[i];
            axv[2*i]   = fa.x; ayv[2*i]   = fa.y;
            axv[2*i+1] = fa.z; ayv[2*i+1] = fa.w;
            bxv[2*i]   = fb.x; byv[2*i]   = fb.y;
            bxv[2*i+1] = fb.z; byv[2*i+1] = fb.w;
        }

        // ---- shoelace areas (vertices CCW by construction) ----
        float area_a = 0.f, area_b = 0.f;
        #pragma unroll
        for (int i = 0; i < NP; i++) {
            int j = (i + 1) & 7;
            area_a += axv[i]*ayv[j] - ayv[i]*axv[j];
            area_b += bxv[i]*byv[j] - byv[i]*bxv[j];
        }
        area_a *= 0.5f; area_b *= 0.5f;

        // ---- edge vectors (const-indexed registers) ----
        float eax[NP], eay[NP], ebx[NP], eby[NP];
        #pragma unroll
        for (int j = 0; j < NP; j++) {
            int k = (j + 1) & 7;
            eax[j] = axv[k] - axv[j]; eay[j] = ayv[k] - ayv[j];
            ebx[j] = bxv[k] - bxv[j]; eby[j] = byv[k] - byv[j];
        }

        // ---- candidate generation (branch-free compaction into smem) ----
        int   cnt = 0;
        float sx = 0.f, sy = 0.f;

        // A vertices inside B
        #pragma unroll
        for (int i = 0; i < NP; i++) {
            bool in = true;
            #pragma unroll
            for (int j = 0; j < NP; j++) {
                float cr = ebx[j]*(ayv[i]-byv[j]) - eby[j]*(axv[i]-bxv[j]);
                in = in && (cr >= -1e-6f);
            }
            int wp = cnt < MAXC-1 ? cnt : MAXC-1;
            s_cx[wp][tid] = axv[i]; s_cy[wp][tid] = ayv[i];
            if (in) { sx += axv[i]; sy += ayv[i]; cnt++; }
        }
        // B vertices inside A
        #pragma unroll
        for (int i = 0; i < NP; i++) {
            bool in = true;
            #pragma unroll
            for (int j = 0; j < NP; j++) {
                float cr = eax[j]*(byv[i]-ayv[j]) - eay[j]*(bxv[i]-axv[j]);
                in = in && (cr >= -1e-6f);
            }
            int wp = cnt < MAXC-1 ? cnt : MAXC-1;
            s_cx[wp][tid] = bxv[i]; s_cy[wp][tid] = byv[i];
            if (in) { sx += bxv[i]; sy += byv[i]; cnt++; }
        }
        // edge-edge intersections: straight-line, predicated accept
        #pragma unroll
        for (int i = 0; i < NP; i++) {
            #pragma unroll
            for (int j = 0; j < NP; j++) {
                float d1x = eax[i], d1y = eay[i];
                float d2x = ebx[j], d2y = eby[j];
                float denom = d1x*d2y - d1y*d2x;
                float rx = bxv[j] - axv[i], ry = byv[j] - ayv[i];
                float tn = rx*d2y - ry*d2x;
                float un = rx*d1y - ry*d1x;
                float dd  = fabsf(denom);
                float sg  = (denom < 0.f) ? -1.f : 1.f;
                float tn2 = sg * tn, un2 = sg * un;
                bool ok = (dd >= 1e-9f) && (tn2 >= 0.f) && (tn2 <= dd)
                                        && (un2 >= 0.f) && (un2 <= dd);
                float t  = __fdividef(tn, denom);
                float ix = axv[i] + t*d1x, iy = ayv[i] + t*d1y;
                int wp = cnt < MAXC-1 ? cnt : MAXC-1;
                s_cx[wp][tid] = ix; s_cy[wp][tid] = iy;
                if (ok) { sx += ix; sy += iy; cnt++; }
            }
        }

        // ---- intersection area: pseudo-angle successor scan (no sort) ----
        float inter = 0.f;
        if (cnt >= 3) {
            float inv = 1.f / (float)cnt;
            float ctx = sx * inv, cty = sy * inv;
            #pragma unroll 1
            for (int i = 0; i < cnt; i++) {
                float dx = s_cx[i][tid] - ctx, dy = s_cy[i][tid] - cty;
                float s  = fabsf(dx) + fabsf(dy);
                float r  = (s > 0.f) ? __fdividef(dx, s) : 1.f;
                s_an[i][tid] = (dy >= 0.f) ? (1.f - r) : (r - 1.f);
            }
            // each point's angular successor = min positive cyclic delta;
            // identical cycle as the sorted polygon -> identical area.
            float ssum = 0.f;
            #pragma unroll 1
            for (int i = 0; i < cnt; i++) {
                float ai  = s_an[i][tid];
                float cxi = s_cx[i][tid], cyi = s_cy[i][tid];
                float best = 4.5f; int bj = 0;
                #pragma unroll 1
                for (int j = 0; j < cnt; j++) {
                    float d = s_an[j][tid] - ai;
                    d = (d <= 0.f) ? d + 4.f : d;      // wrap (span = 4)
                    if (d < best) { best = d; bj = j; }
                }
                ssum += cxi * s_cy[bj][tid] - cyi * s_cx[bj][tid];
            }
            inter = fmaxf(0.5f * ssum, 0.f);
        }

        // ---- convex hull of all 16 points (pure-register Jarvis march) ----
        int   si  = 0;
        float spx = axv[0], spy = ayv[0];
        #pragma unroll
        for (int i = 1; i < 16; i++) {
            float pix = (i < 8) ? axv[i] : bxv[i-8];
            float piy = (i < 8) ? ayv[i] : byv[i-8];
            bool better = (piy < spy) || (piy == spy && pix < spx);
            if (better) { si = i; spx = pix; spy = piy; }
        }
        float acc = 0.f, cpx = spx, cpy = spy;
        #pragma unroll 1
        for (int step = 0; step < 16; step++) {
            int   nxt = -1;
            float vnx = 0.f, vny = 0.f, nd2 = 0.f, nxx = 0.f, nxy = 0.f;
            #pragma unroll
            for (int p = 0; p < 16; p++) {
                float pxp = (p < 8) ? axv[p] : bxv[p-8];
                float pyp = (p < 8) ? ayv[p] : byv[p-8];
                float vx = pxp - cpx, vy = pyp - cpy;
                float d2 = vx*vx + vy*vy;
                if (d2 >= 1e-16f) {
                    bool take;
                    if (nxt < 0) take = true;
                    else {
                        float cr = vnx*vy - vny*vx;
                        take = (cr < 0.f) || (cr == 0.f && d2 > nd2);
                    }
                    if (take) { nxt = p; vnx = vx; vny = vy; nd2 = d2;
                                nxx = pxp; nxy = pyp; }
                }
            }
            if (nxt < 0) break;
            acc += cpx*nxy - cpy*nxx;
            if (nxt == si) break;
            cpx = nxx; cpy = nxy;
        }
        float ch = 0.5f * acc;

        // ---- CIoU ----
        float uni = area_a + area_b - inter;
        float iou = inter / uni;
        val = (double)(iou - (ch - uni) / ch);
    }

    // ---- deterministic block reduction (4 warps) ----
    #pragma unroll
    for (int o = 16; o > 0; o >>= 1)
        val += __shfl_down_sync(0xffffffffu, val, o);
    __shared__ double ws[NT / 32];
    __shared__ bool is_last;
    int lane = threadIdx.x & 31;
    int w    = threadIdx.x >> 5;
    if (lane == 0) ws[w] = val;
    __syncthreads();
    if (w == 0) {
        val = (lane < (NT / 32)) ? ws[lane] : 0.0;
        #pragma unroll
        for (int o = 2; o > 0; o >>= 1)
            val += __shfl_down_sync(0xffffffffu, val, o);
        if (lane == 0) g_part[blockIdx.x] = val;
    }

    // ---- last block folds the partials (deterministic fixed-order sum) ----
    __threadfence();
    if (threadIdx.x == 0) {
        unsigned int t = atomicAdd(&g_ticket, 1u);
        is_last = (t == NBLOCKS - 1);
    }
    __syncthreads();
    if (is_last) {
        __threadfence();
        double v = 0.0;
        for (int i = threadIdx.x; i < NBLOCKS; i += NT) v += g_part[i];
        #pragma unroll
        for (int o = 16; o > 0; o >>= 1)
            v += __shfl_down_sync(0xffffffffu, v, o);
        if (lane == 0) ws[w] = v;
        __syncthreads();
        if (w == 0) {
            v = (lane < (NT / 32)) ? ws[lane] : 0.0;
            #pragma unroll
            for (int o = 2; o > 0; o >>= 1)
                v += __shfl_down_sync(0xffffffffu, v, o);
            if (lane == 0) {
                out[0] = (float)(v / (double)NB);
                g_ticket = 0;   // reset for next graph replay
            }
        }
    }
}

extern "C" void kernel_launch(void* const* d_in, const int* in_sizes, int n_in,
                              void* d_out, int out_size) {
    const float* a = (const float*)d_in[0];
    const float* b = (const float*)d_in[1];
    ciou_kernel<<<NBLOCKS, NT>>>(a, b, (float*)d_out);
}

// round 8
// speedup vs baseline: 1.2816x; 1.2816x over previous
#include <cuda_runtime.h>
#include <math.h>

#define NB 262144
#define NP 8
#define NT 128
#define NBLOCKS (NB / NT)
#define MAXC 24

__device__ double g_part[NBLOCKS];
__device__ unsigned int g_ticket;

__global__ void __launch_bounds__(NT, 5)
ciou_kernel(const float* __restrict__ A, const float* __restrict__ Bm,
            float* __restrict__ out) {
    // [slot][tid] layout: bank index = tid%32 -> conflict-free even when
    // lanes use different slot indices.
    __shared__ float s_cx[MAXC][NT];
    __shared__ float s_cy[MAXC][NT];
    __shared__ float s_an[MAXC][NT];

    const int tid = threadIdx.x;
    const int b   = blockIdx.x * NT + tid;

    double val;
    {
        // ---- load both octagons (registers; all indexing below is const) ----
        float axv[NP], ayv[NP], bxv[NP], byv[NP];
        const float4* pa4 = (const float4*)(A  + (size_t)b * 16);
        const float4* pb4 = (const float4*)(Bm + (size_t)b * 16);
        #pragma unroll
        for (int i = 0; i < 4; i++) {
            float4 fa = pa4[i], fb = pb4[i];
            axv[2*i]   = fa.x; ayv[2*i]   = fa.y;
            axv[2*i+1] = fa.z; ayv[2*i+1] = fa.w;
            bxv[2*i]   = fb.x; byv[2*i]   = fb.y;
            bxv[2*i+1] = fb.z; byv[2*i+1] = fb.w;
        }

        // ---- shoelace areas (vertices CCW by construction) ----
        float area_a = 0.f, area_b = 0.f;
        #pragma unroll
        for (int i = 0; i < NP; i++) {
            int j = (i + 1) & 7;
            area_a += axv[i]*ayv[j] - ayv[i]*axv[j];
            area_b += bxv[i]*byv[j] - byv[i]*bxv[j];
        }
        area_a *= 0.5f; area_b *= 0.5f;

        // ---- candidate generation (branch-free compaction into smem) ----
        // Edge vectors are recomputed inline (1 SUB each) -> no edge arrays,
        // peak live set stays within the 102-reg cap, zero spill.
        int   cnt = 0;
        float sx = 0.f, sy = 0.f;

        // A vertices inside B
        #pragma unroll
        for (int i = 0; i < NP; i++) {
            bool in = true;
            #pragma unroll
            for (int j = 0; j < NP; j++) {
                int k = (j + 1) & 7;
                float ex = bxv[k] - bxv[j], ey = byv[k] - byv[j];
                float cr = ex*(ayv[i]-byv[j]) - ey*(axv[i]-bxv[j]);
                in = in && (cr >= -1e-6f);
            }
            int wp = cnt < MAXC-1 ? cnt : MAXC-1;
            s_cx[wp][tid] = axv[i]; s_cy[wp][tid] = ayv[i];
            if (in) { sx += axv[i]; sy += ayv[i]; cnt++; }
        }
        // B vertices inside A
        #pragma unroll
        for (int i = 0; i < NP; i++) {
            bool in = true;
            #pragma unroll
            for (int j = 0; j < NP; j++) {
                int k = (j + 1) & 7;
                float ex = axv[k] - axv[j], ey = ayv[k] - ayv[j];
                float cr = ex*(byv[i]-ayv[j]) - ey*(bxv[i]-axv[j]);
                in = in && (cr >= -1e-6f);
            }
            int wp = cnt < MAXC-1 ? cnt : MAXC-1;
            s_cx[wp][tid] = bxv[i]; s_cy[wp][tid] = byv[i];
            if (in) { sx += bxv[i]; sy += byv[i]; cnt++; }
        }
        // edge-edge intersections: straight-line, predicated accept
        #pragma unroll
        for (int i = 0; i < NP; i++) {
            {
                int ik = (i + 1) & 7;
                float d1x = axv[ik] - axv[i], d1y = ayv[ik] - ayv[i];
                #pragma unroll
                for (int j = 0; j < NP; j++) {
                    int jk = (j + 1) & 7;
                    float d2x = bxv[jk] - bxv[j], d2y = byv[jk] - byv[j];
                    float denom = d1x*d2y - d1y*d2x;
                    float rx = bxv[j] - axv[i], ry = byv[j] - ayv[i];
                    float tn = rx*d2y - ry*d2x;
                    float un = rx*d1y - ry*d1x;
                    float dd  = fabsf(denom);
                    float sg  = (denom < 0.f) ? -1.f : 1.f;
                    float tn2 = sg * tn, un2 = sg * un;
                    bool ok = (dd >= 1e-9f) && (tn2 >= 0.f) && (tn2 <= dd)
                                            && (un2 >= 0.f) && (un2 <= dd);
                    float t  = __fdividef(tn, denom);
                    float ix = axv[i] + t*d1x, iy = ayv[i] + t*d1y;
                    int wp = cnt < MAXC-1 ? cnt : MAXC-1;
                    s_cx[wp][tid] = ix; s_cy[wp][tid] = iy;
                    if (ok) { sx += ix; sy += iy; cnt++; }
                }
            }
            // scheduling anchor: keep the 8 i-groups from being fused into
            // one giant live range by the scheduler
            asm volatile("" ::: "memory");
        }

        // ---- intersection area: pseudo-angle successor scan (no sort) ----
        float inter = 0.f;
        if (cnt >= 3) {
            float inv = 1.f / (float)cnt;
            float ctx = sx * inv, cty = sy * inv;
            #pragma unroll 1
            for (int i = 0; i < cnt; i++) {
                float dx = s_cx[i][tid] - ctx, dy = s_cy[i][tid] - cty;
                float s  = fabsf(dx) + fabsf(dy);
                float r  = (s > 0.f) ? __fdividef(dx, s) : 1.f;
                s_an[i][tid] = (dy >= 0.f) ? (1.f - r) : (r - 1.f);
            }
            // each point's angular successor = min positive cyclic delta;
            // identical cycle as the sorted polygon -> identical area.
            float ssum = 0.f;
            #pragma unroll 1
            for (int i = 0; i < cnt; i++) {
                float ai  = s_an[i][tid];
                float cxi = s_cx[i][tid], cyi = s_cy[i][tid];
                float best = 4.5f; int bj = 0;
                #pragma unroll 1
                for (int j = 0; j < cnt; j++) {
                    float d = s_an[j][tid] - ai;
                    d = (d <= 0.f) ? d + 4.f : d;      // wrap (span = 4)
                    if (d < best) { best = d; bj = j; }
                }
                ssum += cxi * s_cy[bj][tid] - cyi * s_cx[bj][tid];
            }
            inter = fmaxf(0.5f * ssum, 0.f);
        }

        // ---- convex hull of all 16 points (pure-register Jarvis march) ----
        int   si  = 0;
        float spx = axv[0], spy = ayv[0];
        #pragma unroll
        for (int i = 1; i < 16; i++) {
            float pix = (i < 8) ? axv[i] : bxv[i-8];
            float piy = (i < 8) ? ayv[i] : byv[i-8];
            bool better = (piy < spy) || (piy == spy && pix < spx);
            if (better) { si = i; spx = pix; spy = piy; }
        }
        float acc = 0.f, cpx = spx, cpy = spy;
        #pragma unroll 1
        for (int step = 0; step < 16; step++) {
            int   nxt = -1;
            float vnx = 0.f, vny = 0.f, nd2 = 0.f, nxx = 0.f, nxy = 0.f;
            #pragma unroll
            for (int p = 0; p < 16; p++) {
                float pxp = (p < 8) ? axv[p] : bxv[p-8];
                float pyp = (p < 8) ? ayv[p] : byv[p-8];
                float vx = pxp - cpx, vy = pyp - cpy;
                float d2 = vx*vx + vy*vy;
                if (d2 >= 1e-16f) {
                    bool take;
                    if (nxt < 0) take = true;
                    else {
                        float cr = vnx*vy - vny*vx;
                        take = (cr < 0.f) || (cr == 0.f && d2 > nd2);
                    }
                    if (take) { nxt = p; vnx = vx; vny = vy; nd2 = d2;
                                nxx = pxp; nxy = pyp; }
                }
            }
            if (nxt < 0) break;
            acc += cpx*nxy - cpy*nxx;
            if (nxt == si) break;
            cpx = nxx; cpy = nxy;
        }
        float ch = 0.5f * acc;

        // ---- CIoU ----
        float uni = area_a + area_b - inter;
        float iou = inter / uni;
        val = (double)(iou - (ch - uni) / ch);
    }

    // ---- deterministic block reduction (4 warps) ----
    #pragma unroll
    for (int o = 16; o > 0; o >>= 1)
        val += __shfl_down_sync(0xffffffffu, val, o);
    __shared__ double ws[NT / 32];
    __shared__ bool is_last;
    int lane = threadIdx.x & 31;
    int w    = threadIdx.x >> 5;
    if (lane == 0) ws[w] = val;
    __syncthreads();
    if (w == 0) {
        val = (lane < (NT / 32)) ? ws[lane] : 0.0;
        #pragma unroll
        for (int o = 2; o > 0; o >>= 1)
            val += __shfl_down_sync(0xffffffffu, val, o);
        if (lane == 0) g_part[blockIdx.x] = val;
    }

    // ---- last block folds the partials (deterministic fixed-order sum) ----
    __threadfence();
    if (threadIdx.x == 0) {
        unsigned int t = atomicAdd(&g_ticket, 1u);
        is_last = (t == NBLOCKS - 1);
    }
    __syncthreads();
    if (is_last) {
        __threadfence();
        double v = 0.0;
        for (int i = threadIdx.x; i < NBLOCKS; i += NT) v += g_part[i];
        #pragma unroll
        for (int o = 16; o > 0; o >>= 1)
            v += __shfl_down_sync(0xffffffffu, v, o);
        if (lane == 0) ws[w] = v;
        __syncthreads();
        if (w == 0) {
            v = (lane < (NT / 32)) ? ws[lane] : 0.0;
            #pragma unroll
            for (int o = 2; o > 0; o >>= 1)
                v += __shfl_down_sync(0xffffffffu, v, o);
            if (lane == 0) {
                out[0] = (float)(v / (double)NB);
                g_ticket = 0;   // reset for next graph replay
            }
        }
    }
}

extern "C" void kernel_launch(void* const* d_in, const int* in_sizes, int n_in,
                              void* d_out, int out_size) {
    const float* a = (const float*)d_in[0];
    const float* b = (const float*)d_in[1];
    ciou_kernel<<<NBLOCKS, NT>>>(a, b, (float*)d_out);
}

// round 9
// speedup vs baseline: 1.9929x; 1.5550x over previous
#include <cuda_runtime.h>
#include <math.h>

#define NB 262144
#define NP 8
#define NT 256
#define NBLOCKS (NB / NT)
#define MAXV 24

__device__ double g_part[NBLOCKS];
__device__ unsigned int g_ticket;

// One Sutherland-Hodgman clip pass against the half-plane left of (o, o+e).
// Hardened: clamped writes, result capped at MAXV. Division only used when a
// sign crossing is flagged (then dp - dc is provably nonzero).
__device__ __forceinline__ int clip_one(
    float ox, float oy, float ex, float ey,
    const float* __restrict__ sxv, const float* __restrict__ syv,
    float* __restrict__ dxv, float* __restrict__ dyv, int nv)
{
    int m = 0;
    float pxp = sxv[nv - 1], pyp = syv[nv - 1];
    float dp  = ex * (pyp - oy) - ey * (pxp - ox);
    #pragma unroll 1
    for (int i = 0; i < nv; i++) {
        float cxp = sxv[i], cyp = syv[i];
        float dc  = ex * (cyp - oy) - ey * (cxp - ox);
        if ((dp < 0.f) != (dc < 0.f)) {
            float t = __fdividef(dp, dp - dc);      // flagged -> dp-dc != 0
            int wp = m < MAXV - 1 ? m : MAXV - 1;
            dxv[wp] = pxp + t * (cxp - pxp);
            dyv[wp] = pyp + t * (cyp - pyp);
            m++;
        }
        if (dc >= 0.f) {
            int wp = m < MAXV - 1 ? m : MAXV - 1;
            dxv[wp] = cxp; dyv[wp] = cyp;
            m++;
        }
        pxp = cxp; pyp = cyp; dp = dc;
    }
    return m < MAXV ? m : MAXV;
}

__global__ void __launch_bounds__(NT)
ciou_kernel(const float* __restrict__ A, const float* __restrict__ Bm,
            float* __restrict__ out) {
    const int tid = threadIdx.x;
    const int b   = blockIdx.x * NT + tid;

    double val;
    {
        // ---- load both octagons (registers; const indexing everywhere) ----
        float axv[NP], ayv[NP], bxv[NP], byv[NP];
        const float4* pa4 = (const float4*)(A  + (size_t)b * 16);
        const float4* pb4 = (const float4*)(Bm + (size_t)b * 16);
        #pragma unroll
        for (int i = 0; i < 4; i++) {
            float4 fa = pa4[i], fb = pb4[i];
            axv[2*i]   = fa.x; ayv[2*i]   = fa.y;
            axv[2*i+1] = fa.z; ayv[2*i+1] = fa.w;
            bxv[2*i]   = fb.x; byv[2*i]   = fb.y;
            bxv[2*i+1] = fb.z; byv[2*i+1] = fb.w;
        }

        // ---- shoelace areas (vertices CCW by construction) ----
        float area_a = 0.f, area_b = 0.f;
        #pragma unroll
        for (int i = 0; i < NP; i++) {
            int j = (i + 1) & 7;
            area_a += axv[i]*ayv[j] - ayv[i]*axv[j];
            area_b += bxv[i]*byv[j] - byv[i]*bxv[j];
        }
        area_a *= 0.5f; area_b *= 0.5f;

        // ---- intersection area: Sutherland-Hodgman, A clipped by B ----
        // Local ping-pong buffers (L1-cached; no smem so L1 stays full-size).
        float v0x[MAXV], v0y[MAXV], v1x[MAXV], v1y[MAXV];
        #pragma unroll
        for (int i = 0; i < NP; i++) { v0x[i] = axv[i]; v0y[i] = ayv[i]; }
        int nv = NP;

        #pragma unroll
        for (int e = 0; e < NP; e++) {          // e compile-time: B coords stay regs
            if (nv >= 3) {
                int k = (e + 1) & 7;
                float ox = bxv[e], oy = byv[e];
                float ex = bxv[k] - ox, ey = byv[k] - oy;
                if (e & 1) nv = clip_one(ox, oy, ex, ey, v1x, v1y, v0x, v0y, nv);
                else       nv = clip_one(ox, oy, ex, ey, v0x, v0y, v1x, v1y, nv);
            } else nv = 0;
        }
        // 8 passes (even count) -> final polygon sits in v0

        float inter = 0.f;
        if (nv >= 3) {
            float s = 0.f;
            float pxp = v0x[nv - 1], pyp = v0y[nv - 1];
            #pragma unroll 1
            for (int i = 0; i < nv; i++) {
                float cxp = v0x[i], cyp = v0y[i];
                s += pxp * cyp - pyp * cxp;
                pxp = cxp; pyp = cyp;
            }
            inter = fmaxf(0.5f * s, 0.f);
        }

        // ---- convex hull of all 16 points (pure-register Jarvis march) ----
        int   si  = 0;
        float spx = axv[0], spy = ayv[0];
        #pragma unroll
        for (int i = 1; i < 16; i++) {
            float pix = (i < 8) ? axv[i] : bxv[i-8];
            float piy = (i < 8) ? ayv[i] : byv[i-8];
            bool better = (piy < spy) || (piy == spy && pix < spx);
            if (better) { si = i; spx = pix; spy = piy; }
        }
        float acc = 0.f, cpx = spx, cpy = spy;
        #pragma unroll 1
        for (int step = 0; step < 16; step++) {
            int   nxt = -1;
            float vnx = 0.f, vny = 0.f, nd2 = 0.f, nxx = 0.f, nxy = 0.f;
            #pragma unroll
            for (int p = 0; p < 16; p++) {
                float pxp = (p < 8) ? axv[p] : bxv[p-8];
                float pyp = (p < 8) ? ayv[p] : byv[p-8];
                float vx = pxp - cpx, vy = pyp - cpy;
                float d2 = vx*vx + vy*vy;
                if (d2 >= 1e-16f) {
                    bool take;
                    if (nxt < 0) take = true;
                    else {
                        float cr = vnx*vy - vny*vx;
                        take = (cr < 0.f) || (cr == 0.f && d2 > nd2);
                    }
                    if (take) { nxt = p; vnx = vx; vny = vy; nd2 = d2;
                                nxx = pxp; nxy = pyp; }
                }
            }
            if (nxt < 0) break;
            acc += cpx*nxy - cpy*nxx;
            if (nxt == si) break;
            cpx = nxx; cpy = nxy;
        }
        float ch = 0.5f * acc;

        // ---- CIoU ----
        float uni = area_a + area_b - inter;
        float iou = inter / uni;
        val = (double)(iou - (ch - uni) / ch);
    }

    // ---- deterministic block reduction (8 warps) ----
    #pragma unroll
    for (int o = 16; o > 0; o >>= 1)
        val += __shfl_down_sync(0xffffffffu, val, o);
    __shared__ double ws[NT / 32];
    __shared__ bool is_last;
    int lane = threadIdx.x & 31;
    int w    = threadIdx.x >> 5;
    if (lane == 0) ws[w] = val;
    __syncthreads();
    if (w == 0) {
        val = (lane < (NT / 32)) ? ws[lane] : 0.0;
        #pragma unroll
        for (int o = 4; o > 0; o >>= 1)
            val += __shfl_down_sync(0xffffffffu, val, o);
        if (lane == 0) g_part[blockIdx.x] = val;
    }

    // ---- last block folds the partials (deterministic fixed-order sum) ----
    __threadfence();
    if (threadIdx.x == 0) {
        unsigned int t = atomicAdd(&g_ticket, 1u);
        is_last = (t == NBLOCKS - 1);
    }
    __syncthreads();
    if (is_last) {
        __threadfence();
        double v = 0.0;
        for (int i = threadIdx.x; i < NBLOCKS; i += NT) v += g_part[i];
        #pragma unroll
        for (int o = 16; o > 0; o >>= 1)
            v += __shfl_down_sync(0xffffffffu, v, o);
        if (lane == 0) ws[w] = v;
        __syncthreads();
        if (w == 0) {
            v = (lane < (NT / 32)) ? ws[lane] : 0.0;
            #pragma unroll
            for (int o = 4; o > 0; o >>= 1)
                v += __shfl_down_sync(0xffffffffu, v, o);
            if (lane == 0) {
                out[0] = (float)(v / (double)NB);
                g_ticket = 0;   // reset for next graph replay
            }
        }
    }
}

extern "C" void kernel_launch(void* const* d_in, const int* in_sizes, int n_in,
                              void* d_out, int out_size) {
    const float* a = (const float*)d_in[0];
    const float* b = (const float*)d_in[1];
    ciou_kernel<<<NBLOCKS, NT>>>(a, b, (float*)d_out);
}